// round 10
// baseline (speedup 1.0000x reference)
#include <cuda_runtime.h>
#include <cmath>
#include <cstdint>

#define N_LEVELS 16
#define TBL_STRIDE 524288u   // 2^19 entries per level
#define OUT_COMPS 35         // 3 (x passthrough) + 16*2 feats
#define THREADS 256
#define HASH_MASK 524287u    // 2^19 - 1; levels >= 6 are always fully hashed

struct Params {
    float res[N_LEVELS];
    unsigned hms[N_LEVELS];
    unsigned long long magic[N_LEVELS];
};

// Lemire fastmod: n % d with M = 2^64/d + 1 (exact for all n < 2^32)
__device__ __forceinline__ unsigned fastmod(unsigned n, unsigned d, unsigned long long M) {
    unsigned long long low = M * (unsigned long long)n;
    return (unsigned)__umul64hi(low, (unsigned long long)d);
}

__global__ __launch_bounds__(THREADS, 6)
void hashgrid_kernel(const float* __restrict__ x,
                     const float2* __restrict__ tables,
                     float* __restrict__ out,
                     Params prm) {
    __shared__ float stage[THREADS * OUT_COMPS];

    const int pt = blockIdx.x * THREADS + threadIdx.x;

    // Streaming reads: x is touched exactly once; keep it out of L2 residency.
    const float x0 = __ldcs(&x[pt * 3 + 0]);
    const float x1 = __ldcs(&x[pt * 3 + 1]);
    const float x2 = __ldcs(&x[pt * 3 + 2]);

    float* my = &stage[threadIdx.x * OUT_COMPS];
    my[0] = x0; my[1] = x1; my[2] = x2;

    const unsigned P1 = 2654435761u;
    const unsigned P2 = 805459861u;

#pragma unroll
    for (int l = 0; l < N_LEVELS; l++) {
        const float r = prm.res[l];
        const float2* __restrict__ tb = tables + (size_t)l * TBL_STRIDE;

        const float xs0 = x0 * r, xs1 = x1 * r, xs2 = x2 * r;
        const float fl0 = floorf(xs0), fl1 = floorf(xs1), fl2 = floorf(xs2);
        const float fx = xs0 - fl0, fy = xs1 - fl1, fz = xs2 - fl2;

        const unsigned a0 = (unsigned)(int)fl0;
        const unsigned a1 = a0 + 1u;
        const unsigned b0 = (unsigned)(int)fl1 * P1;
        const unsigned c0 = (unsigned)(int)fl2 * P2;
        const unsigned hb[2] = {b0, b0 + P1};
        const unsigned hc[2] = {c0, c0 + P2};

        const bool a0even = (a0 & 1u) == 0u;

        // e[n], n = ix | iy<<1 | iz<<2
        float2 e[8];

        if (l >= 6) {
            // Fully hashed (d = 2^19). a0 even => h1 = h0^1 => indices
            // {m0&~1, (m0&~1)+1}: one aligned float4; m0's parity selects halves.
            if (a0even) {
#pragma unroll
                for (int pr = 0; pr < 4; pr++) {
                    const int iy = pr & 1, iz = pr >> 1;
                    const unsigned m0 = (a0 ^ hb[iy] ^ hc[iz]) & HASH_MASK;
                    const float4 q = __ldcg((const float4*)tb + (m0 >> 1));
                    const float2 lo = make_float2(q.x, q.y);
                    const float2 hi = make_float2(q.z, q.w);
                    const bool odd = (m0 & 1u) != 0u;
                    const int n = (iy << 1) | (iz << 2);
                    e[n]     = odd ? hi : lo;   // corner ix=0 is index m0
                    e[n | 1] = odd ? lo : hi;   // corner ix=1 is index m0^1
                }
            } else {
#pragma unroll
                for (int pr = 0; pr < 4; pr++) {
                    const int iy = pr & 1, iz = pr >> 1;
                    const unsigned hbc = hb[iy] ^ hc[iz];
                    const int n = (iy << 1) | (iz << 2);
                    e[n]     = __ldcg(tb + ((a0 ^ hbc) & HASH_MASK));
                    e[n | 1] = __ldcg(tb + ((a1 ^ hbc) & HASH_MASK));
                }
            }
        } else if (l != 3 && l != 4) {
            // Mod levels with EVEN hms (l = 0,1,2,5: 4096,10648,27000,512000).
            // a0 even => h1 = h0^1; even-d mod preserves parity, so the pair is
            // always {m0&~1, (m0&~1)+1}. One fastmod + one aligned float4;
            // m0's parity selects which half is corner ix=0.
            const unsigned d = prm.hms[l];
            const unsigned long long M = prm.magic[l];
            if (a0even) {
#pragma unroll
                for (int pr = 0; pr < 4; pr++) {
                    const int iy = pr & 1, iz = pr >> 1;
                    const unsigned m0 = fastmod(a0 ^ hb[iy] ^ hc[iz], d, M);
                    const float4 q = (l < 3) ? __ldg((const float4*)tb + (m0 >> 1))
                                             : __ldcg((const float4*)tb + (m0 >> 1));
                    const float2 lo = make_float2(q.x, q.y);
                    const float2 hi = make_float2(q.z, q.w);
                    const bool odd = (m0 & 1u) != 0u;
                    const int n = (iy << 1) | (iz << 2);
                    e[n]     = odd ? hi : lo;
                    e[n | 1] = odd ? lo : hi;
                }
            } else {
#pragma unroll
                for (int pr = 0; pr < 4; pr++) {
                    const int iy = pr & 1, iz = pr >> 1;
                    const unsigned hbc = hb[iy] ^ hc[iz];
                    const unsigned m0 = fastmod(a0 ^ hbc, d, M);
                    const unsigned m1 = fastmod(a1 ^ hbc, d, M);
                    const int n = (iy << 1) | (iz << 2);
                    e[n]     = (l < 3) ? __ldg(tb + m0) : __ldcg(tb + m0);
                    e[n | 1] = (l < 3) ? __ldg(tb + m1) : __ldcg(tb + m1);
                }
            }
        } else {
            // Mod levels with ODD hms (l = 3,4: 68921, 185193): parity not
            // preserved; merge only when the runtime check passes.
            const unsigned d = prm.hms[l];
            const unsigned long long M = prm.magic[l];
#pragma unroll
            for (int pr = 0; pr < 4; pr++) {
                const int iy = pr & 1, iz = pr >> 1;
                const unsigned hbc = hb[iy] ^ hc[iz];
                const unsigned m0 = fastmod(a0 ^ hbc, d, M);
                const unsigned m1 = fastmod(a1 ^ hbc, d, M);
                const int n = (iy << 1) | (iz << 2);
                if ((m0 ^ m1) == 1u) {
                    const float4 q = __ldcg((const float4*)tb + (m0 >> 1));
                    const float2 lo = make_float2(q.x, q.y);
                    const float2 hi = make_float2(q.z, q.w);
                    const bool odd = (m0 & 1u) != 0u;
                    e[n]     = odd ? hi : lo;
                    e[n | 1] = odd ? lo : hi;
                } else {
                    e[n]     = __ldcg(tb + m0);
                    e[n | 1] = __ldcg(tb + m1);
                }
            }
        }

        const float wx[2] = {1.0f - fx, fx};
        const float wy[2] = {1.0f - fy, fy};
        const float wz[2] = {1.0f - fz, fz};

        float acc0 = 0.0f, acc1 = 0.0f;
#pragma unroll
        for (int n = 0; n < 8; n++) {
            const float w = wx[n & 1] * wy[(n >> 1) & 1] * wz[n >> 2];
            acc0 = fmaf(e[n].x, w, acc0);
            acc1 = fmaf(e[n].y, w, acc1);
        }
        my[3 + 2 * l]     = acc0;
        my[3 + 2 * l + 1] = acc1;
    }

    __syncwarp();

    // Coalesced writeout: each warp copies its 32 rows (32*35 floats = 4480 B,
    // 16B-aligned in smem and gmem) as float4 streaming stores (write-once
    // data: evict-first so it doesn't displace the table working set in L2).
    const int lane = threadIdx.x & 31;
    const int warp_first = (blockIdx.x * THREADS) + (threadIdx.x & ~31);
    const float4* src = (const float4*)&stage[(threadIdx.x & ~31) * OUT_COMPS];
    float4* dst = (float4*)(out + (size_t)warp_first * OUT_COMPS);
#pragma unroll
    for (int j = lane; j < (32 * OUT_COMPS) / 4; j += 32) {
        __stcs(&dst[j], src[j]);
    }
}

extern "C" void kernel_launch(void* const* d_in, const int* in_sizes, int n_in,
                              void* d_out, int out_size) {
    const float*  x      = (const float*)d_in[0];
    const float2* tables = (const float2*)d_in[1];
    float*        out    = (float*)d_out;

    // Level params via the exact same double-precision libm sequence as the
    // Python reference (same machine/libm => bit-identical results).
    Params prm;
    const double beta = exp((log(2048.0) - log(16.0)) / 15.0);
    for (int l = 0; l < N_LEVELS; l++) {
        const double r = floor(16.0 * pow(beta, (double)l));
        prm.res[l] = (float)r;
        const long long ri = (long long)r;
        long long h3 = ri * ri * ri;
        if (h3 > 524288LL) h3 = 524288LL;
        const unsigned d = (unsigned)h3;
        prm.hms[l] = d;
        prm.magic[l] = 0xFFFFFFFFFFFFFFFFull / d + 1ull;
    }

    const int npts = in_sizes[0] / 3;
    const int blocks = (npts + THREADS - 1) / THREADS;
    hashgrid_kernel<<<blocks, THREADS>>>(x, tables, out, prm);
}

// round 11
// speedup vs baseline: 1.6768x; 1.6768x over previous
#include <cuda_runtime.h>
#include <cmath>
#include <cstdint>

#define N_LEVELS 16
#define TBL_STRIDE 524288u   // 2^19 entries per level
#define OUT_COMPS 35         // 3 (x passthrough) + 16*2 feats
#define THREADS 256
#define HASH_MASK 524287u    // 2^19 - 1; levels >= 6 are always fully hashed

struct Params {
    float res[N_LEVELS];
    unsigned hms[N_LEVELS];
    unsigned long long magic[N_LEVELS];
};

// Lemire fastmod: n % d with M = 2^64/d + 1 (exact for all n < 2^32)
__device__ __forceinline__ unsigned fastmod(unsigned n, unsigned d, unsigned long long M) {
    unsigned long long low = M * (unsigned long long)n;
    return (unsigned)__umul64hi(low, (unsigned long long)d);
}

__global__ __launch_bounds__(THREADS)
void hashgrid_kernel(const float* __restrict__ x,
                     const float2* __restrict__ tables,
                     float* __restrict__ out,
                     Params prm) {
    __shared__ float stage[THREADS * OUT_COMPS];

    const int pt = blockIdx.x * THREADS + threadIdx.x;

    const float x0 = x[pt * 3 + 0];
    const float x1 = x[pt * 3 + 1];
    const float x2 = x[pt * 3 + 2];

    float* my = &stage[threadIdx.x * OUT_COMPS];
    my[0] = x0; my[1] = x1; my[2] = x2;

    const unsigned P1 = 2654435761u;
    const unsigned P2 = 805459861u;

#pragma unroll
    for (int l = 0; l < N_LEVELS; l++) {
        const float r = prm.res[l];
        const float2* __restrict__ tb = tables + (size_t)l * TBL_STRIDE;

        const float xs0 = x0 * r, xs1 = x1 * r, xs2 = x2 * r;
        const float fl0 = floorf(xs0), fl1 = floorf(xs1), fl2 = floorf(xs2);
        const float fx = xs0 - fl0, fy = xs1 - fl1, fz = xs2 - fl2;

        const unsigned a0 = (unsigned)(int)fl0;
        const unsigned a1 = a0 + 1u;
        const unsigned b0 = (unsigned)(int)fl1 * P1;
        const unsigned c0 = (unsigned)(int)fl2 * P2;
        const unsigned hb[2] = {b0, b0 + P1};
        const unsigned hc[2] = {c0, c0 + P2};

        const bool a0even = (a0 & 1u) == 0u;

        // e[n], n = ix | iy<<1 | iz<<2
        float2 e[8];

        if (l >= 6) {
            // Fully hashed (d = 2^19). a0 even => h1 = h0^1 => indices
            // {m0&~1, (m0&~1)+1}: one aligned float4; m0's parity selects halves.
            if (a0even) {
#pragma unroll
                for (int pr = 0; pr < 4; pr++) {
                    const int iy = pr & 1, iz = pr >> 1;
                    const unsigned m0 = (a0 ^ hb[iy] ^ hc[iz]) & HASH_MASK;
                    const float4 q = __ldcg((const float4*)tb + (m0 >> 1));
                    const float2 lo = make_float2(q.x, q.y);
                    const float2 hi = make_float2(q.z, q.w);
                    const bool odd = (m0 & 1u) != 0u;
                    const int n = (iy << 1) | (iz << 2);
                    e[n]     = odd ? hi : lo;   // corner ix=0 is index m0
                    e[n | 1] = odd ? lo : hi;   // corner ix=1 is index m0^1
                }
            } else {
#pragma unroll
                for (int pr = 0; pr < 4; pr++) {
                    const int iy = pr & 1, iz = pr >> 1;
                    const unsigned hbc = hb[iy] ^ hc[iz];
                    const int n = (iy << 1) | (iz << 2);
                    e[n]     = __ldcg(tb + ((a0 ^ hbc) & HASH_MASK));
                    e[n | 1] = __ldcg(tb + ((a1 ^ hbc) & HASH_MASK));
                }
            }
        } else if (l != 3 && l != 4) {
            // Mod levels with EVEN hms (l = 0,1,2,5: 4096,10648,27000,512000).
            // a0 even => h1 = h0^1; even-d mod preserves parity, so the pair is
            // always {m0&~1, (m0&~1)+1}. One fastmod + one aligned float4;
            // m0's parity selects which half is corner ix=0.
            const unsigned d = prm.hms[l];
            const unsigned long long M = prm.magic[l];
            if (a0even) {
#pragma unroll
                for (int pr = 0; pr < 4; pr++) {
                    const int iy = pr & 1, iz = pr >> 1;
                    const unsigned m0 = fastmod(a0 ^ hb[iy] ^ hc[iz], d, M);
                    const float4 q = (l < 3) ? __ldg((const float4*)tb + (m0 >> 1))
                                             : __ldcg((const float4*)tb + (m0 >> 1));
                    const float2 lo = make_float2(q.x, q.y);
                    const float2 hi = make_float2(q.z, q.w);
                    const bool odd = (m0 & 1u) != 0u;
                    const int n = (iy << 1) | (iz << 2);
                    e[n]     = odd ? hi : lo;
                    e[n | 1] = odd ? lo : hi;
                }
            } else {
#pragma unroll
                for (int pr = 0; pr < 4; pr++) {
                    const int iy = pr & 1, iz = pr >> 1;
                    const unsigned hbc = hb[iy] ^ hc[iz];
                    const unsigned m0 = fastmod(a0 ^ hbc, d, M);
                    const unsigned m1 = fastmod(a1 ^ hbc, d, M);
                    const int n = (iy << 1) | (iz << 2);
                    e[n]     = (l < 3) ? __ldg(tb + m0) : __ldcg(tb + m0);
                    e[n | 1] = (l < 3) ? __ldg(tb + m1) : __ldcg(tb + m1);
                }
            }
        } else {
            // Mod levels with ODD hms (l = 3,4: 68921, 185193): parity not
            // preserved; merge only when the runtime check passes.
            const unsigned d = prm.hms[l];
            const unsigned long long M = prm.magic[l];
#pragma unroll
            for (int pr = 0; pr < 4; pr++) {
                const int iy = pr & 1, iz = pr >> 1;
                const unsigned hbc = hb[iy] ^ hc[iz];
                const unsigned m0 = fastmod(a0 ^ hbc, d, M);
                const unsigned m1 = fastmod(a1 ^ hbc, d, M);
                const int n = (iy << 1) | (iz << 2);
                if ((m0 ^ m1) == 1u) {
                    const float4 q = __ldcg((const float4*)tb + (m0 >> 1));
                    const float2 lo = make_float2(q.x, q.y);
                    const float2 hi = make_float2(q.z, q.w);
                    const bool odd = (m0 & 1u) != 0u;
                    e[n]     = odd ? hi : lo;
                    e[n | 1] = odd ? lo : hi;
                } else {
                    e[n]     = __ldcg(tb + m0);
                    e[n | 1] = __ldcg(tb + m1);
                }
            }
        }

        const float wx[2] = {1.0f - fx, fx};
        const float wy[2] = {1.0f - fy, fy};
        const float wz[2] = {1.0f - fz, fz};

        float acc0 = 0.0f, acc1 = 0.0f;
#pragma unroll
        for (int n = 0; n < 8; n++) {
            const float w = wx[n & 1] * wy[(n >> 1) & 1] * wz[n >> 2];
            acc0 = fmaf(e[n].x, w, acc0);
            acc1 = fmaf(e[n].y, w, acc1);
        }
        my[3 + 2 * l]     = acc0;
        my[3 + 2 * l + 1] = acc1;
    }

    __syncwarp();

    // Coalesced writeout: each warp copies its 32 rows (32*35 floats = 4480 B,
    // 16B-aligned in smem and gmem) as float4 streaming stores (write-once
    // data: evict-first so it doesn't displace the table working set in L2).
    const int lane = threadIdx.x & 31;
    const int warp_first = (blockIdx.x * THREADS) + (threadIdx.x & ~31);
    const float4* src = (const float4*)&stage[(threadIdx.x & ~31) * OUT_COMPS];
    float4* dst = (float4*)(out + (size_t)warp_first * OUT_COMPS);
#pragma unroll
    for (int j = lane; j < (32 * OUT_COMPS) / 4; j += 32) {
        __stcs(&dst[j], src[j]);
    }
}

extern "C" void kernel_launch(void* const* d_in, const int* in_sizes, int n_in,
                              void* d_out, int out_size) {
    const float*  x      = (const float*)d_in[0];
    const float2* tables = (const float2*)d_in[1];
    float*        out    = (float*)d_out;

    // Level params via the exact same double-precision libm sequence as the
    // Python reference (same machine/libm => bit-identical results).
    Params prm;
    const double beta = exp((log(2048.0) - log(16.0)) / 15.0);
    for (int l = 0; l < N_LEVELS; l++) {
        const double r = floor(16.0 * pow(beta, (double)l));
        prm.res[l] = (float)r;
        const long long ri = (long long)r;
        long long h3 = ri * ri * ri;
        if (h3 > 524288LL) h3 = 524288LL;
        const unsigned d = (unsigned)h3;
        prm.hms[l] = d;
        prm.magic[l] = 0xFFFFFFFFFFFFFFFFull / d + 1ull;
    }

    const int npts = in_sizes[0] / 3;
    const int blocks = (npts + THREADS - 1) / THREADS;
    hashgrid_kernel<<<blocks, THREADS>>>(x, tables, out, prm);
}

// round 12
// speedup vs baseline: 1.7258x; 1.0292x over previous
#include <cuda_runtime.h>
#include <cmath>
#include <cstdint>

#define N_LEVELS 16
#define TBL_STRIDE 524288u   // 2^19 entries per level
#define OUT_COMPS 35         // 3 (x passthrough) + 16*2 feats
#define THREADS 256
#define HASH_MASK 524287u    // 2^19 - 1; levels >= 6 are always fully hashed

struct Params {
    float res[N_LEVELS];
    unsigned hms[N_LEVELS];
    unsigned long long magic[N_LEVELS];
};

// Lemire fastmod: n % d with M = 2^64/d + 1 (exact for all n < 2^32)
__device__ __forceinline__ unsigned fastmod(unsigned n, unsigned d, unsigned long long M) {
    unsigned long long low = M * (unsigned long long)n;
    return (unsigned)__umul64hi(low, (unsigned long long)d);
}

// Per-level geometry for the interleaved hashed path.
struct LevelGeom {
    unsigned a0, hb0, hb1, hc0, hc1;
    float fx, fy, fz;
};

__device__ __forceinline__ LevelGeom make_geom(float x0, float x1, float x2, float r) {
    const unsigned P1 = 2654435761u;
    const unsigned P2 = 805459861u;
    LevelGeom g;
    const float xs0 = x0 * r, xs1 = x1 * r, xs2 = x2 * r;
    const float fl0 = floorf(xs0), fl1 = floorf(xs1), fl2 = floorf(xs2);
    g.fx = xs0 - fl0; g.fy = xs1 - fl1; g.fz = xs2 - fl2;
    g.a0  = (unsigned)(int)fl0;
    g.hb0 = (unsigned)(int)fl1 * P1;  g.hb1 = g.hb0 + P1;
    g.hc0 = (unsigned)(int)fl2 * P2;  g.hc1 = g.hc0 + P2;
    return g;
}

// Issue gather loads for one fully-hashed level (mask-mod).
__device__ __forceinline__ void load_hashed(const LevelGeom& g,
                                            const float2* __restrict__ tb,
                                            float2 e[8]) {
    const unsigned hb[2] = {g.hb0, g.hb1};
    const unsigned hc[2] = {g.hc0, g.hc1};
    if ((g.a0 & 1u) == 0u) {
#pragma unroll
        for (int pr = 0; pr < 4; pr++) {
            const int iy = pr & 1, iz = pr >> 1;
            const unsigned m0 = (g.a0 ^ hb[iy] ^ hc[iz]) & HASH_MASK;
            const float4 q = __ldcg((const float4*)tb + (m0 >> 1));
            const float2 lo = make_float2(q.x, q.y);
            const float2 hi = make_float2(q.z, q.w);
            const bool odd = (m0 & 1u) != 0u;
            const int n = (iy << 1) | (iz << 2);
            e[n]     = odd ? hi : lo;
            e[n | 1] = odd ? lo : hi;
        }
    } else {
#pragma unroll
        for (int pr = 0; pr < 4; pr++) {
            const int iy = pr & 1, iz = pr >> 1;
            const unsigned hbc = hb[iy] ^ hc[iz];
            const int n = (iy << 1) | (iz << 2);
            e[n]     = __ldcg(tb + ((g.a0 ^ hbc) & HASH_MASK));
            e[n | 1] = __ldcg(tb + (((g.a0 + 1u) ^ hbc) & HASH_MASK));
        }
    }
}

__device__ __forceinline__ void consume(const LevelGeom& g, const float2 e[8],
                                        float* dst) {
    const float wx[2] = {1.0f - g.fx, g.fx};
    const float wy[2] = {1.0f - g.fy, g.fy};
    const float wz[2] = {1.0f - g.fz, g.fz};
    float acc0 = 0.0f, acc1 = 0.0f;
#pragma unroll
    for (int n = 0; n < 8; n++) {
        const float w = wx[n & 1] * wy[(n >> 1) & 1] * wz[n >> 2];
        acc0 = fmaf(e[n].x, w, acc0);
        acc1 = fmaf(e[n].y, w, acc1);
    }
    dst[0] = acc0;
    dst[1] = acc1;
}

__global__ __launch_bounds__(THREADS)
void hashgrid_kernel(const float* __restrict__ x,
                     const float2* __restrict__ tables,
                     float* __restrict__ out,
                     Params prm) {
    __shared__ float stage[THREADS * OUT_COMPS];

    const int pt = blockIdx.x * THREADS + threadIdx.x;

    const float x0 = x[pt * 3 + 0];
    const float x1 = x[pt * 3 + 1];
    const float x2 = x[pt * 3 + 2];

    float* my = &stage[threadIdx.x * OUT_COMPS];
    my[0] = x0; my[1] = x1; my[2] = x2;

    // ── Levels 0-5: mod-indexed (even-d fast path; odd-d checked) ──
#pragma unroll
    for (int l = 0; l < 6; l++) {
        const LevelGeom g = make_geom(x0, x1, x2, prm.res[l]);
        const float2* __restrict__ tb = tables + (size_t)l * TBL_STRIDE;
        const unsigned d = prm.hms[l];
        const unsigned long long M = prm.magic[l];
        const unsigned hb[2] = {g.hb0, g.hb1};
        const unsigned hc[2] = {g.hc0, g.hc1};

        float2 e[8];
        if (l != 3 && l != 4) {
            // EVEN hms (4096, 10648, 27000, 512000): a0 even => pair is always
            // {m0&~1, (m0&~1)+1}; parity of m0 selects halves.
            if ((g.a0 & 1u) == 0u) {
#pragma unroll
                for (int pr = 0; pr < 4; pr++) {
                    const int iy = pr & 1, iz = pr >> 1;
                    const unsigned m0 = fastmod(g.a0 ^ hb[iy] ^ hc[iz], d, M);
                    const float4 q = (l < 3) ? __ldg((const float4*)tb + (m0 >> 1))
                                             : __ldcg((const float4*)tb + (m0 >> 1));
                    const float2 lo = make_float2(q.x, q.y);
                    const float2 hi = make_float2(q.z, q.w);
                    const bool odd = (m0 & 1u) != 0u;
                    const int n = (iy << 1) | (iz << 2);
                    e[n]     = odd ? hi : lo;
                    e[n | 1] = odd ? lo : hi;
                }
            } else {
#pragma unroll
                for (int pr = 0; pr < 4; pr++) {
                    const int iy = pr & 1, iz = pr >> 1;
                    const unsigned hbc = hb[iy] ^ hc[iz];
                    const unsigned m0 = fastmod(g.a0 ^ hbc, d, M);
                    const unsigned m1 = fastmod(g.a0 + 1u ^ hbc, d, M) ;
                    const int n = (iy << 1) | (iz << 2);
                    e[n]     = (l < 3) ? __ldg(tb + m0) : __ldcg(tb + m0);
                    e[n | 1] = (l < 3) ? __ldg(tb + m1) : __ldcg(tb + m1);
                }
            }
        } else {
            // ODD hms (68921, 185193): runtime merge check.
#pragma unroll
            for (int pr = 0; pr < 4; pr++) {
                const int iy = pr & 1, iz = pr >> 1;
                const unsigned hbc = hb[iy] ^ hc[iz];
                const unsigned m0 = fastmod(g.a0 ^ hbc, d, M);
                const unsigned m1 = fastmod((g.a0 + 1u) ^ hbc, d, M);
                const int n = (iy << 1) | (iz << 2);
                if ((m0 ^ m1) == 1u) {
                    const float4 q = __ldcg((const float4*)tb + (m0 >> 1));
                    const float2 lo = make_float2(q.x, q.y);
                    const float2 hi = make_float2(q.z, q.w);
                    const bool odd = (m0 & 1u) != 0u;
                    e[n]     = odd ? hi : lo;
                    e[n | 1] = odd ? lo : hi;
                } else {
                    e[n]     = __ldcg(tb + m0);
                    e[n | 1] = __ldcg(tb + m1);
                }
            }
        }
        consume(g, e, &my[3 + 2 * l]);
    }

    // ── Levels 6-15 (fully hashed): interleave pairs to double loads in flight ──
#pragma unroll
    for (int lp = 6; lp < 16; lp += 2) {
        const LevelGeom gA = make_geom(x0, x1, x2, prm.res[lp]);
        const LevelGeom gB = make_geom(x0, x1, x2, prm.res[lp + 1]);
        const float2* __restrict__ tbA = tables + (size_t)lp * TBL_STRIDE;
        const float2* __restrict__ tbB = tables + (size_t)(lp + 1) * TBL_STRIDE;

        float2 eA[8], eB[8];
        load_hashed(gA, tbA, eA);     // both levels' loads issued before
        load_hashed(gB, tbB, eB);     // either level's FMAs consume them
        consume(gA, eA, &my[3 + 2 * lp]);
        consume(gB, eB, &my[3 + 2 * (lp + 1)]);
    }

    __syncwarp();

    // Coalesced writeout: each warp copies its 32 rows (32*35 floats = 4480 B,
    // 16B-aligned in smem and gmem) as float4 streaming stores.
    const int lane = threadIdx.x & 31;
    const int warp_first = (blockIdx.x * THREADS) + (threadIdx.x & ~31);
    const float4* src = (const float4*)&stage[(threadIdx.x & ~31) * OUT_COMPS];
    float4* dst = (float4*)(out + (size_t)warp_first * OUT_COMPS);
#pragma unroll
    for (int j = lane; j < (32 * OUT_COMPS) / 4; j += 32) {
        __stcs(&dst[j], src[j]);
    }
}

extern "C" void kernel_launch(void* const* d_in, const int* in_sizes, int n_in,
                              void* d_out, int out_size) {
    const float*  x      = (const float*)d_in[0];
    const float2* tables = (const float2*)d_in[1];
    float*        out    = (float*)d_out;

    // Level params via the exact same double-precision libm sequence as the
    // Python reference (same machine/libm => bit-identical results).
    Params prm;
    const double beta = exp((log(2048.0) - log(16.0)) / 15.0);
    for (int l = 0; l < N_LEVELS; l++) {
        const double r = floor(16.0 * pow(beta, (double)l));
        prm.res[l] = (float)r;
        const long long ri = (long long)r;
        long long h3 = ri * ri * ri;
        if (h3 > 524288LL) h3 = 524288LL;
        const unsigned d = (unsigned)h3;
        prm.hms[l] = d;
        prm.magic[l] = 0xFFFFFFFFFFFFFFFFull / d + 1ull;
    }

    const int npts = in_sizes[0] / 3;
    const int blocks = (npts + THREADS - 1) / THREADS;
    hashgrid_kernel<<<blocks, THREADS>>>(x, tables, out, prm);
}

// round 13
// speedup vs baseline: 1.7259x; 1.0001x over previous
#include <cuda_runtime.h>
#include <cmath>
#include <cstdint>

#define N_LEVELS 16
#define TBL_STRIDE 524288u   // 2^19 entries per level
#define OUT_COMPS 35         // 3 (x passthrough) + 16*2 feats
#define THREADS 256
#define HASH_MASK 524287u    // 2^19 - 1; levels >= 6 are always fully hashed

struct Params {
    float res[N_LEVELS];
    unsigned hms[N_LEVELS];
    unsigned long long magic[N_LEVELS];
};

// Lemire fastmod: n % d with M = 2^64/d + 1 (exact for all n < 2^32)
__device__ __forceinline__ unsigned fastmod(unsigned n, unsigned d, unsigned long long M) {
    unsigned long long low = M * (unsigned long long)n;
    return (unsigned)__umul64hi(low, (unsigned long long)d);
}

// Per-level geometry.
struct LevelGeom {
    unsigned a0, hb0, hb1, hc0, hc1;
    float fx, fy, fz;
};

__device__ __forceinline__ LevelGeom make_geom(float x0, float x1, float x2, float r) {
    const unsigned P1 = 2654435761u;
    const unsigned P2 = 805459861u;
    LevelGeom g;
    const float xs0 = x0 * r, xs1 = x1 * r, xs2 = x2 * r;
    const float fl0 = floorf(xs0), fl1 = floorf(xs1), fl2 = floorf(xs2);
    g.fx = xs0 - fl0; g.fy = xs1 - fl1; g.fz = xs2 - fl2;
    g.a0  = (unsigned)(int)fl0;
    g.hb0 = (unsigned)(int)fl1 * P1;  g.hb1 = g.hb0 + P1;
    g.hc0 = (unsigned)(int)fl2 * P2;  g.hc1 = g.hc0 + P2;
    return g;
}

// Fully-hashed level (d = 2^19, mask-mod).
__device__ __forceinline__ void load_hashed(const LevelGeom& g,
                                            const float2* __restrict__ tb,
                                            float2 e[8]) {
    const unsigned hb[2] = {g.hb0, g.hb1};
    const unsigned hc[2] = {g.hc0, g.hc1};
    if ((g.a0 & 1u) == 0u) {
#pragma unroll
        for (int pr = 0; pr < 4; pr++) {
            const int iy = pr & 1, iz = pr >> 1;
            const unsigned m0 = (g.a0 ^ hb[iy] ^ hc[iz]) & HASH_MASK;
            const float4 q = __ldcg((const float4*)tb + (m0 >> 1));
            const float2 lo = make_float2(q.x, q.y);
            const float2 hi = make_float2(q.z, q.w);
            const bool odd = (m0 & 1u) != 0u;
            const int n = (iy << 1) | (iz << 2);
            e[n]     = odd ? hi : lo;
            e[n | 1] = odd ? lo : hi;
        }
    } else {
#pragma unroll
        for (int pr = 0; pr < 4; pr++) {
            const int iy = pr & 1, iz = pr >> 1;
            const unsigned hbc = hb[iy] ^ hc[iz];
            const int n = (iy << 1) | (iz << 2);
            e[n]     = __ldcg(tb + ((g.a0 ^ hbc) & HASH_MASK));
            e[n | 1] = __ldcg(tb + (((g.a0 + 1u) ^ hbc) & HASH_MASK));
        }
    }
}

// Mod level. EVEN_D: even hms => a0-even guarantees aligned pair (parity
// preserved by even-d mod). Otherwise runtime merge check. L1: allocate in L1.
template <bool EVEN_D, bool L1>
__device__ __forceinline__ void load_mod(const LevelGeom& g,
                                         const float2* __restrict__ tb,
                                         unsigned d, unsigned long long M,
                                         float2 e[8]) {
    const unsigned hb[2] = {g.hb0, g.hb1};
    const unsigned hc[2] = {g.hc0, g.hc1};
    if (EVEN_D && (g.a0 & 1u) == 0u) {
#pragma unroll
        for (int pr = 0; pr < 4; pr++) {
            const int iy = pr & 1, iz = pr >> 1;
            const unsigned m0 = fastmod(g.a0 ^ hb[iy] ^ hc[iz], d, M);
            const float4 q = L1 ? __ldg((const float4*)tb + (m0 >> 1))
                                : __ldcg((const float4*)tb + (m0 >> 1));
            const float2 lo = make_float2(q.x, q.y);
            const float2 hi = make_float2(q.z, q.w);
            const bool odd = (m0 & 1u) != 0u;
            const int n = (iy << 1) | (iz << 2);
            e[n]     = odd ? hi : lo;
            e[n | 1] = odd ? lo : hi;
        }
    } else if (EVEN_D) {
#pragma unroll
        for (int pr = 0; pr < 4; pr++) {
            const int iy = pr & 1, iz = pr >> 1;
            const unsigned hbc = hb[iy] ^ hc[iz];
            const unsigned m0 = fastmod(g.a0 ^ hbc, d, M);
            const unsigned m1 = fastmod((g.a0 + 1u) ^ hbc, d, M);
            const int n = (iy << 1) | (iz << 2);
            e[n]     = L1 ? __ldg(tb + m0) : __ldcg(tb + m0);
            e[n | 1] = L1 ? __ldg(tb + m1) : __ldcg(tb + m1);
        }
    } else {
#pragma unroll
        for (int pr = 0; pr < 4; pr++) {
            const int iy = pr & 1, iz = pr >> 1;
            const unsigned hbc = hb[iy] ^ hc[iz];
            const unsigned m0 = fastmod(g.a0 ^ hbc, d, M);
            const unsigned m1 = fastmod((g.a0 + 1u) ^ hbc, d, M);
            const int n = (iy << 1) | (iz << 2);
            if ((m0 ^ m1) == 1u) {
                const float4 q = __ldcg((const float4*)tb + (m0 >> 1));
                const float2 lo = make_float2(q.x, q.y);
                const float2 hi = make_float2(q.z, q.w);
                const bool odd = (m0 & 1u) != 0u;
                e[n]     = odd ? hi : lo;
                e[n | 1] = odd ? lo : hi;
            } else {
                e[n]     = __ldcg(tb + m0);
                e[n | 1] = __ldcg(tb + m1);
            }
        }
    }
}

__device__ __forceinline__ void consume(const LevelGeom& g, const float2 e[8],
                                        float* dst) {
    const float wx[2] = {1.0f - g.fx, g.fx};
    const float wy[2] = {1.0f - g.fy, g.fy};
    const float wz[2] = {1.0f - g.fz, g.fz};
    float acc0 = 0.0f, acc1 = 0.0f;
#pragma unroll
    for (int n = 0; n < 8; n++) {
        const float w = wx[n & 1] * wy[(n >> 1) & 1] * wz[n >> 2];
        acc0 = fmaf(e[n].x, w, acc0);
        acc1 = fmaf(e[n].y, w, acc1);
    }
    dst[0] = acc0;
    dst[1] = acc1;
}

__global__ __launch_bounds__(THREADS)
void hashgrid_kernel(const float* __restrict__ x,
                     const float2* __restrict__ tables,
                     float* __restrict__ out,
                     Params prm) {
    __shared__ float stage[THREADS * OUT_COMPS];

    const int pt = blockIdx.x * THREADS + threadIdx.x;

    const float x0 = x[pt * 3 + 0];
    const float x1 = x[pt * 3 + 1];
    const float x2 = x[pt * 3 + 2];

    float* my = &stage[threadIdx.x * OUT_COMPS];
    my[0] = x0; my[1] = x1; my[2] = x2;

    const float2* __restrict__ tbase = tables;

    // ── Mod levels, pair-interleaved: (0,1) (2,3) (4,5) ──
    // hms: l0=4096(e) l1=10648(e) l2=27000(e) l3=68921(o) l4=185193(o) l5=512000(e)
    {
        float2 eA[8], eB[8];
        {   // pair (0,1): both even-d, L1
            const LevelGeom gA = make_geom(x0, x1, x2, prm.res[0]);
            const LevelGeom gB = make_geom(x0, x1, x2, prm.res[1]);
            load_mod<true, true>(gA, tbase + 0 * (size_t)TBL_STRIDE, prm.hms[0], prm.magic[0], eA);
            load_mod<true, true>(gB, tbase + 1 * (size_t)TBL_STRIDE, prm.hms[1], prm.magic[1], eB);
            consume(gA, eA, &my[3 + 0]);
            consume(gB, eB, &my[3 + 2]);
        }
        {   // pair (2,3): even-d L1, odd-d L2
            const LevelGeom gA = make_geom(x0, x1, x2, prm.res[2]);
            const LevelGeom gB = make_geom(x0, x1, x2, prm.res[3]);
            load_mod<true, true>(gA, tbase + 2 * (size_t)TBL_STRIDE, prm.hms[2], prm.magic[2], eA);
            load_mod<false, false>(gB, tbase + 3 * (size_t)TBL_STRIDE, prm.hms[3], prm.magic[3], eB);
            consume(gA, eA, &my[3 + 4]);
            consume(gB, eB, &my[3 + 6]);
        }
        {   // pair (4,5): odd-d L2, even-d L2
            const LevelGeom gA = make_geom(x0, x1, x2, prm.res[4]);
            const LevelGeom gB = make_geom(x0, x1, x2, prm.res[5]);
            load_mod<false, false>(gA, tbase + 4 * (size_t)TBL_STRIDE, prm.hms[4], prm.magic[4], eA);
            load_mod<true, false>(gB, tbase + 5 * (size_t)TBL_STRIDE, prm.hms[5], prm.magic[5], eB);
            consume(gA, eA, &my[3 + 8]);
            consume(gB, eB, &my[3 + 10]);
        }
    }

    // ── Hashed levels 6-15, pair-interleaved ──
#pragma unroll
    for (int lp = 6; lp < 16; lp += 2) {
        const LevelGeom gA = make_geom(x0, x1, x2, prm.res[lp]);
        const LevelGeom gB = make_geom(x0, x1, x2, prm.res[lp + 1]);
        const float2* __restrict__ tbA = tbase + (size_t)lp * TBL_STRIDE;
        const float2* __restrict__ tbB = tbase + (size_t)(lp + 1) * TBL_STRIDE;

        float2 eA[8], eB[8];
        load_hashed(gA, tbA, eA);
        load_hashed(gB, tbB, eB);
        consume(gA, eA, &my[3 + 2 * lp]);
        consume(gB, eB, &my[3 + 2 * (lp + 1)]);
    }

    __syncwarp();

    // Coalesced writeout: each warp copies its 32 rows (32*35 floats = 4480 B,
    // 16B-aligned in smem and gmem) as float4 streaming stores.
    const int lane = threadIdx.x & 31;
    const int warp_first = (blockIdx.x * THREADS) + (threadIdx.x & ~31);
    const float4* src = (const float4*)&stage[(threadIdx.x & ~31) * OUT_COMPS];
    float4* dst = (float4*)(out + (size_t)warp_first * OUT_COMPS);
#pragma unroll
    for (int j = lane; j < (32 * OUT_COMPS) / 4; j += 32) {
        __stcs(&dst[j], src[j]);
    }
}

extern "C" void kernel_launch(void* const* d_in, const int* in_sizes, int n_in,
                              void* d_out, int out_size) {
    const float*  x      = (const float*)d_in[0];
    const float2* tables = (const float2*)d_in[1];
    float*        out    = (float*)d_out;

    // Level params via the exact same double-precision libm sequence as the
    // Python reference (same machine/libm => bit-identical results).
    Params prm;
    const double beta = exp((log(2048.0) - log(16.0)) / 15.0);
    for (int l = 0; l < N_LEVELS; l++) {
        const double r = floor(16.0 * pow(beta, (double)l));
        prm.res[l] = (float)r;
        const long long ri = (long long)r;
        long long h3 = ri * ri * ri;
        if (h3 > 524288LL) h3 = 524288LL;
        const unsigned d = (unsigned)h3;
        prm.hms[l] = d;
        prm.magic[l] = 0xFFFFFFFFFFFFFFFFull / d + 1ull;
    }

    const int npts = in_sizes[0] / 3;
    const int blocks = (npts + THREADS - 1) / THREADS;
    hashgrid_kernel<<<blocks, THREADS>>>(x, tables, out, prm);
}

// round 14
// speedup vs baseline: 1.7565x; 1.0177x over previous
#include <cuda_runtime.h>
#include <cmath>
#include <cstdint>

#define N_LEVELS 16
#define TBL_STRIDE 524288u   // 2^19 entries per level
#define OUT_COMPS 35         // 3 (x passthrough) + 16*2 feats
#define THREADS 256
#define HASH_MASK 524287u    // 2^19 - 1; levels >= 6 are always fully hashed

struct Params {
    float res[N_LEVELS];
    unsigned hms[N_LEVELS];
    unsigned long long magic[N_LEVELS];
};

// Lemire fastmod: n % d with M = 2^64/d + 1 (exact for all n < 2^32)
__device__ __forceinline__ unsigned fastmod(unsigned n, unsigned d, unsigned long long M) {
    unsigned long long low = M * (unsigned long long)n;
    return (unsigned)__umul64hi(low, (unsigned long long)d);
}

// Per-level geometry.
struct LevelGeom {
    unsigned a0, hb0, hb1, hc0, hc1;
    float fx, fy, fz;
};

__device__ __forceinline__ LevelGeom make_geom(float x0, float x1, float x2, float r) {
    const unsigned P1 = 2654435761u;
    const unsigned P2 = 805459861u;
    LevelGeom g;
    const float xs0 = x0 * r, xs1 = x1 * r, xs2 = x2 * r;
    const float fl0 = floorf(xs0), fl1 = floorf(xs1), fl2 = floorf(xs2);
    g.fx = xs0 - fl0; g.fy = xs1 - fl1; g.fz = xs2 - fl2;
    g.a0  = (unsigned)(int)fl0;
    g.hb0 = (unsigned)(int)fl1 * P1;  g.hb1 = g.hb0 + P1;
    g.hc0 = (unsigned)(int)fl2 * P2;  g.hc1 = g.hc0 + P2;
    return g;
}

// Fully-hashed level (d = 2^19, mask-mod).
__device__ __forceinline__ void load_hashed(const LevelGeom& g,
                                            const float2* __restrict__ tb,
                                            float2 e[8]) {
    const unsigned hb[2] = {g.hb0, g.hb1};
    const unsigned hc[2] = {g.hc0, g.hc1};
    if ((g.a0 & 1u) == 0u) {
#pragma unroll
        for (int pr = 0; pr < 4; pr++) {
            const int iy = pr & 1, iz = pr >> 1;
            const unsigned m0 = (g.a0 ^ hb[iy] ^ hc[iz]) & HASH_MASK;
            const float4 q = __ldcg((const float4*)tb + (m0 >> 1));
            const float2 lo = make_float2(q.x, q.y);
            const float2 hi = make_float2(q.z, q.w);
            const bool odd = (m0 & 1u) != 0u;
            const int n = (iy << 1) | (iz << 2);
            e[n]     = odd ? hi : lo;
            e[n | 1] = odd ? lo : hi;
        }
    } else {
#pragma unroll
        for (int pr = 0; pr < 4; pr++) {
            const int iy = pr & 1, iz = pr >> 1;
            const unsigned hbc = hb[iy] ^ hc[iz];
            const int n = (iy << 1) | (iz << 2);
            e[n]     = __ldcg(tb + ((g.a0 ^ hbc) & HASH_MASK));
            e[n | 1] = __ldcg(tb + (((g.a0 + 1u) ^ hbc) & HASH_MASK));
        }
    }
}

// Mod level. EVEN_D: even hms => a0-even guarantees aligned pair (parity
// preserved by even-d mod). Otherwise runtime merge check. L1: allocate in L1.
template <bool EVEN_D, bool L1>
__device__ __forceinline__ void load_mod(const LevelGeom& g,
                                         const float2* __restrict__ tb,
                                         unsigned d, unsigned long long M,
                                         float2 e[8]) {
    const unsigned hb[2] = {g.hb0, g.hb1};
    const unsigned hc[2] = {g.hc0, g.hc1};
    if (EVEN_D && (g.a0 & 1u) == 0u) {
#pragma unroll
        for (int pr = 0; pr < 4; pr++) {
            const int iy = pr & 1, iz = pr >> 1;
            const unsigned m0 = fastmod(g.a0 ^ hb[iy] ^ hc[iz], d, M);
            const float4 q = L1 ? __ldg((const float4*)tb + (m0 >> 1))
                                : __ldcg((const float4*)tb + (m0 >> 1));
            const float2 lo = make_float2(q.x, q.y);
            const float2 hi = make_float2(q.z, q.w);
            const bool odd = (m0 & 1u) != 0u;
            const int n = (iy << 1) | (iz << 2);
            e[n]     = odd ? hi : lo;
            e[n | 1] = odd ? lo : hi;
        }
    } else if (EVEN_D) {
#pragma unroll
        for (int pr = 0; pr < 4; pr++) {
            const int iy = pr & 1, iz = pr >> 1;
            const unsigned hbc = hb[iy] ^ hc[iz];
            const unsigned m0 = fastmod(g.a0 ^ hbc, d, M);
            const unsigned m1 = fastmod((g.a0 + 1u) ^ hbc, d, M);
            const int n = (iy << 1) | (iz << 2);
            e[n]     = L1 ? __ldg(tb + m0) : __ldcg(tb + m0);
            e[n | 1] = L1 ? __ldg(tb + m1) : __ldcg(tb + m1);
        }
    } else {
#pragma unroll
        for (int pr = 0; pr < 4; pr++) {
            const int iy = pr & 1, iz = pr >> 1;
            const unsigned hbc = hb[iy] ^ hc[iz];
            const unsigned m0 = fastmod(g.a0 ^ hbc, d, M);
            const unsigned m1 = fastmod((g.a0 + 1u) ^ hbc, d, M);
            const int n = (iy << 1) | (iz << 2);
            if ((m0 ^ m1) == 1u) {
                const float4 q = __ldcg((const float4*)tb + (m0 >> 1));
                const float2 lo = make_float2(q.x, q.y);
                const float2 hi = make_float2(q.z, q.w);
                const bool odd = (m0 & 1u) != 0u;
                e[n]     = odd ? hi : lo;
                e[n | 1] = odd ? lo : hi;
            } else {
                e[n]     = __ldcg(tb + m0);
                e[n | 1] = __ldcg(tb + m1);
            }
        }
    }
}

__device__ __forceinline__ void consume(const LevelGeom& g, const float2 e[8],
                                        float* dst) {
    const float wx[2] = {1.0f - g.fx, g.fx};
    const float wy[2] = {1.0f - g.fy, g.fy};
    const float wz[2] = {1.0f - g.fz, g.fz};
    float acc0 = 0.0f, acc1 = 0.0f;
#pragma unroll
    for (int n = 0; n < 8; n++) {
        const float w = wx[n & 1] * wy[(n >> 1) & 1] * wz[n >> 2];
        acc0 = fmaf(e[n].x, w, acc0);
        acc1 = fmaf(e[n].y, w, acc1);
    }
    dst[0] = acc0;
    dst[1] = acc1;
}

__global__ __launch_bounds__(THREADS, 3)
void hashgrid_kernel(const float* __restrict__ x,
                     const float2* __restrict__ tables,
                     float* __restrict__ out,
                     Params prm) {
    __shared__ float stage[THREADS * OUT_COMPS];

    const int pt = blockIdx.x * THREADS + threadIdx.x;

    const float x0 = x[pt * 3 + 0];
    const float x1 = x[pt * 3 + 1];
    const float x2 = x[pt * 3 + 2];

    float* my = &stage[threadIdx.x * OUT_COMPS];
    my[0] = x0; my[1] = x1; my[2] = x2;

    const float2* __restrict__ tbase = tables;

    // ── Mod levels, pair-interleaved: (0,1) (2,3) (4,5) ──
    // hms: l0=4096(e) l1=10648(e) l2=27000(e) l3=68921(o) l4=185193(o) l5=512000(e)
    {
        float2 eA[8], eB[8];
        {   // pair (0,1): both even-d, L1
            const LevelGeom gA = make_geom(x0, x1, x2, prm.res[0]);
            const LevelGeom gB = make_geom(x0, x1, x2, prm.res[1]);
            load_mod<true, true>(gA, tbase + 0 * (size_t)TBL_STRIDE, prm.hms[0], prm.magic[0], eA);
            load_mod<true, true>(gB, tbase + 1 * (size_t)TBL_STRIDE, prm.hms[1], prm.magic[1], eB);
            consume(gA, eA, &my[3 + 0]);
            consume(gB, eB, &my[3 + 2]);
        }
        {   // pair (2,3): even-d L1, odd-d L2
            const LevelGeom gA = make_geom(x0, x1, x2, prm.res[2]);
            const LevelGeom gB = make_geom(x0, x1, x2, prm.res[3]);
            load_mod<true, true>(gA, tbase + 2 * (size_t)TBL_STRIDE, prm.hms[2], prm.magic[2], eA);
            load_mod<false, false>(gB, tbase + 3 * (size_t)TBL_STRIDE, prm.hms[3], prm.magic[3], eB);
            consume(gA, eA, &my[3 + 4]);
            consume(gB, eB, &my[3 + 6]);
        }
        {   // pair (4,5): odd-d L2, even-d L2
            const LevelGeom gA = make_geom(x0, x1, x2, prm.res[4]);
            const LevelGeom gB = make_geom(x0, x1, x2, prm.res[5]);
            load_mod<false, false>(gA, tbase + 4 * (size_t)TBL_STRIDE, prm.hms[4], prm.magic[4], eA);
            load_mod<true, false>(gB, tbase + 5 * (size_t)TBL_STRIDE, prm.hms[5], prm.magic[5], eB);
            consume(gA, eA, &my[3 + 8]);
            consume(gB, eB, &my[3 + 10]);
        }
    }

    // ── Hashed levels 6-14, triple-interleaved: (6,7,8) (9,10,11) (12,13,14) ──
#pragma unroll
    for (int lt = 6; lt < 15; lt += 3) {
        const LevelGeom gA = make_geom(x0, x1, x2, prm.res[lt]);
        const LevelGeom gB = make_geom(x0, x1, x2, prm.res[lt + 1]);
        const LevelGeom gC = make_geom(x0, x1, x2, prm.res[lt + 2]);
        const float2* __restrict__ tbA = tbase + (size_t)lt * TBL_STRIDE;
        const float2* __restrict__ tbB = tbase + (size_t)(lt + 1) * TBL_STRIDE;
        const float2* __restrict__ tbC = tbase + (size_t)(lt + 2) * TBL_STRIDE;

        float2 eA[8], eB[8], eC[8];
        load_hashed(gA, tbA, eA);    // all three levels' loads issued
        load_hashed(gB, tbB, eB);    // before any FMA consumes them
        load_hashed(gC, tbC, eC);
        consume(gA, eA, &my[3 + 2 * lt]);
        consume(gB, eB, &my[3 + 2 * (lt + 1)]);
        consume(gC, eC, &my[3 + 2 * (lt + 2)]);
    }

    // ── Level 15 (single tail) ──
    {
        const LevelGeom g = make_geom(x0, x1, x2, prm.res[15]);
        float2 e[8];
        load_hashed(g, tbase + (size_t)15 * TBL_STRIDE, e);
        consume(g, e, &my[3 + 30]);
    }

    __syncwarp();

    // Coalesced writeout: each warp copies its 32 rows (32*35 floats = 4480 B,
    // 16B-aligned in smem and gmem) as float4 streaming stores.
    const int lane = threadIdx.x & 31;
    const int warp_first = (blockIdx.x * THREADS) + (threadIdx.x & ~31);
    const float4* src = (const float4*)&stage[(threadIdx.x & ~31) * OUT_COMPS];
    float4* dst = (float4*)(out + (size_t)warp_first * OUT_COMPS);
#pragma unroll
    for (int j = lane; j < (32 * OUT_COMPS) / 4; j += 32) {
        __stcs(&dst[j], src[j]);
    }
}

extern "C" void kernel_launch(void* const* d_in, const int* in_sizes, int n_in,
                              void* d_out, int out_size) {
    const float*  x      = (const float*)d_in[0];
    const float2* tables = (const float2*)d_in[1];
    float*        out    = (float*)d_out;

    // Level params via the exact same double-precision libm sequence as the
    // Python reference (same machine/libm => bit-identical results).
    Params prm;
    const double beta = exp((log(2048.0) - log(16.0)) / 15.0);
    for (int l = 0; l < N_LEVELS; l++) {
        const double r = floor(16.0 * pow(beta, (double)l));
        prm.res[l] = (float)r;
        const long long ri = (long long)r;
        long long h3 = ri * ri * ri;
        if (h3 > 524288LL) h3 = 524288LL;
        const unsigned d = (unsigned)h3;
        prm.hms[l] = d;
        prm.magic[l] = 0xFFFFFFFFFFFFFFFFull / d + 1ull;
    }

    const int npts = in_sizes[0] / 3;
    const int blocks = (npts + THREADS - 1) / THREADS;
    hashgrid_kernel<<<blocks, THREADS>>>(x, tables, out, prm);
}

// round 15
// speedup vs baseline: 1.7594x; 1.0016x over previous
#include <cuda_runtime.h>
#include <cmath>
#include <cstdint>

#define N_LEVELS 16
#define TBL_STRIDE 524288u   // 2^19 entries per level
#define OUT_COMPS 35         // 3 (x passthrough) + 16*2 feats
#define THREADS 256
#define HASH_MASK 524287u    // 2^19 - 1; levels >= 6 are always fully hashed

struct Params {
    float res[N_LEVELS];
    unsigned hms[N_LEVELS];
    unsigned long long magic[N_LEVELS];
};

// Lemire fastmod: n % d with M = 2^64/d + 1 (exact for all n < 2^32)
__device__ __forceinline__ unsigned fastmod(unsigned n, unsigned d, unsigned long long M) {
    unsigned long long low = M * (unsigned long long)n;
    return (unsigned)__umul64hi(low, (unsigned long long)d);
}

// Per-level geometry.
struct LevelGeom {
    unsigned a0, hb0, hb1, hc0, hc1;
    float fx, fy, fz;
};

__device__ __forceinline__ LevelGeom make_geom(float x0, float x1, float x2, float r) {
    const unsigned P1 = 2654435761u;
    const unsigned P2 = 805459861u;
    LevelGeom g;
    const float xs0 = x0 * r, xs1 = x1 * r, xs2 = x2 * r;
    const float fl0 = floorf(xs0), fl1 = floorf(xs1), fl2 = floorf(xs2);
    g.fx = xs0 - fl0; g.fy = xs1 - fl1; g.fz = xs2 - fl2;
    g.a0  = (unsigned)(int)fl0;
    g.hb0 = (unsigned)(int)fl1 * P1;  g.hb1 = g.hb0 + P1;
    g.hc0 = (unsigned)(int)fl2 * P2;  g.hc1 = g.hc0 + P2;
    return g;
}

// Fully-hashed level (d = 2^19, mask-mod).
__device__ __forceinline__ void load_hashed(const LevelGeom& g,
                                            const float2* __restrict__ tb,
                                            float2 e[8]) {
    const unsigned hb[2] = {g.hb0, g.hb1};
    const unsigned hc[2] = {g.hc0, g.hc1};
    if ((g.a0 & 1u) == 0u) {
#pragma unroll
        for (int pr = 0; pr < 4; pr++) {
            const int iy = pr & 1, iz = pr >> 1;
            const unsigned m0 = (g.a0 ^ hb[iy] ^ hc[iz]) & HASH_MASK;
            const float4 q = __ldcg((const float4*)tb + (m0 >> 1));
            const float2 lo = make_float2(q.x, q.y);
            const float2 hi = make_float2(q.z, q.w);
            const bool odd = (m0 & 1u) != 0u;
            const int n = (iy << 1) | (iz << 2);
            e[n]     = odd ? hi : lo;
            e[n | 1] = odd ? lo : hi;
        }
    } else {
#pragma unroll
        for (int pr = 0; pr < 4; pr++) {
            const int iy = pr & 1, iz = pr >> 1;
            const unsigned hbc = hb[iy] ^ hc[iz];
            const int n = (iy << 1) | (iz << 2);
            e[n]     = __ldcg(tb + ((g.a0 ^ hbc) & HASH_MASK));
            e[n | 1] = __ldcg(tb + (((g.a0 + 1u) ^ hbc) & HASH_MASK));
        }
    }
}

// Mod level. EVEN_D: even hms => a0-even guarantees aligned pair (parity
// preserved by even-d mod). Otherwise runtime merge check. L1: allocate in L1.
template <bool EVEN_D, bool L1>
__device__ __forceinline__ void load_mod(const LevelGeom& g,
                                         const float2* __restrict__ tb,
                                         unsigned d, unsigned long long M,
                                         float2 e[8]) {
    const unsigned hb[2] = {g.hb0, g.hb1};
    const unsigned hc[2] = {g.hc0, g.hc1};
    if (EVEN_D && (g.a0 & 1u) == 0u) {
#pragma unroll
        for (int pr = 0; pr < 4; pr++) {
            const int iy = pr & 1, iz = pr >> 1;
            const unsigned m0 = fastmod(g.a0 ^ hb[iy] ^ hc[iz], d, M);
            const float4 q = L1 ? __ldg((const float4*)tb + (m0 >> 1))
                                : __ldcg((const float4*)tb + (m0 >> 1));
            const float2 lo = make_float2(q.x, q.y);
            const float2 hi = make_float2(q.z, q.w);
            const bool odd = (m0 & 1u) != 0u;
            const int n = (iy << 1) | (iz << 2);
            e[n]     = odd ? hi : lo;
            e[n | 1] = odd ? lo : hi;
        }
    } else if (EVEN_D) {
#pragma unroll
        for (int pr = 0; pr < 4; pr++) {
            const int iy = pr & 1, iz = pr >> 1;
            const unsigned hbc = hb[iy] ^ hc[iz];
            const unsigned m0 = fastmod(g.a0 ^ hbc, d, M);
            const unsigned m1 = fastmod((g.a0 + 1u) ^ hbc, d, M);
            const int n = (iy << 1) | (iz << 2);
            e[n]     = L1 ? __ldg(tb + m0) : __ldcg(tb + m0);
            e[n | 1] = L1 ? __ldg(tb + m1) : __ldcg(tb + m1);
        }
    } else {
#pragma unroll
        for (int pr = 0; pr < 4; pr++) {
            const int iy = pr & 1, iz = pr >> 1;
            const unsigned hbc = hb[iy] ^ hc[iz];
            const unsigned m0 = fastmod(g.a0 ^ hbc, d, M);
            const unsigned m1 = fastmod((g.a0 + 1u) ^ hbc, d, M);
            const int n = (iy << 1) | (iz << 2);
            if ((m0 ^ m1) == 1u) {
                const float4 q = __ldcg((const float4*)tb + (m0 >> 1));
                const float2 lo = make_float2(q.x, q.y);
                const float2 hi = make_float2(q.z, q.w);
                const bool odd = (m0 & 1u) != 0u;
                e[n]     = odd ? hi : lo;
                e[n | 1] = odd ? lo : hi;
            } else {
                e[n]     = __ldcg(tb + m0);
                e[n | 1] = __ldcg(tb + m1);
            }
        }
    }
}

__device__ __forceinline__ void consume(const LevelGeom& g, const float2 e[8],
                                        float* dst) {
    const float wx[2] = {1.0f - g.fx, g.fx};
    const float wy[2] = {1.0f - g.fy, g.fy};
    const float wz[2] = {1.0f - g.fz, g.fz};
    float acc0 = 0.0f, acc1 = 0.0f;
#pragma unroll
    for (int n = 0; n < 8; n++) {
        const float w = wx[n & 1] * wy[(n >> 1) & 1] * wz[n >> 2];
        acc0 = fmaf(e[n].x, w, acc0);
        acc1 = fmaf(e[n].y, w, acc1);
    }
    dst[0] = acc0;
    dst[1] = acc1;
}

__global__ __launch_bounds__(THREADS, 3)
void hashgrid_kernel(const float* __restrict__ x,
                     const float2* __restrict__ tables,
                     float* __restrict__ out,
                     Params prm) {
    __shared__ float stage[THREADS * OUT_COMPS];

    const int pt = blockIdx.x * THREADS + threadIdx.x;

    const float x0 = x[pt * 3 + 0];
    const float x1 = x[pt * 3 + 1];
    const float x2 = x[pt * 3 + 2];

    float* my = &stage[threadIdx.x * OUT_COMPS];
    my[0] = x0; my[1] = x1; my[2] = x2;

    const float2* __restrict__ tbase = tables;

    // ── Mod levels, pair-interleaved: (0,1) (2,3) (4,5) ──
    // hms: l0=4096(e) l1=10648(e) l2=27000(e) l3=68921(o) l4=185193(o) l5=512000(e)
    {
        float2 eA[8], eB[8];
        {   // pair (0,1): both even-d, L1
            const LevelGeom gA = make_geom(x0, x1, x2, prm.res[0]);
            const LevelGeom gB = make_geom(x0, x1, x2, prm.res[1]);
            load_mod<true, true>(gA, tbase + 0 * (size_t)TBL_STRIDE, prm.hms[0], prm.magic[0], eA);
            load_mod<true, true>(gB, tbase + 1 * (size_t)TBL_STRIDE, prm.hms[1], prm.magic[1], eB);
            consume(gA, eA, &my[3 + 0]);
            consume(gB, eB, &my[3 + 2]);
        }
        {   // pair (2,3): even-d L1, odd-d L2
            const LevelGeom gA = make_geom(x0, x1, x2, prm.res[2]);
            const LevelGeom gB = make_geom(x0, x1, x2, prm.res[3]);
            load_mod<true, true>(gA, tbase + 2 * (size_t)TBL_STRIDE, prm.hms[2], prm.magic[2], eA);
            load_mod<false, false>(gB, tbase + 3 * (size_t)TBL_STRIDE, prm.hms[3], prm.magic[3], eB);
            consume(gA, eA, &my[3 + 4]);
            consume(gB, eB, &my[3 + 6]);
        }
        {   // pair (4,5): odd-d L2, even-d L2
            const LevelGeom gA = make_geom(x0, x1, x2, prm.res[4]);
            const LevelGeom gB = make_geom(x0, x1, x2, prm.res[5]);
            load_mod<false, false>(gA, tbase + 4 * (size_t)TBL_STRIDE, prm.hms[4], prm.magic[4], eA);
            load_mod<true, false>(gB, tbase + 5 * (size_t)TBL_STRIDE, prm.hms[5], prm.magic[5], eB);
            consume(gA, eA, &my[3 + 8]);
            consume(gB, eB, &my[3 + 10]);
        }
    }

    // ── Hashed levels 6-15: depth-3 software-pipelined sliding window.
    // Prologue fills slots with levels 6,7,8; steady state consumes level l-3
    // and immediately issues level l's loads into the freed slot, keeping 2-3
    // levels' gathers in flight at all times (no group-boundary drain).
    {
        LevelGeom g[3];
        float2 e[3][8];

#pragma unroll
        for (int i = 0; i < 3; i++) {
            g[i] = make_geom(x0, x1, x2, prm.res[6 + i]);
            load_hashed(g[i], tbase + (size_t)(6 + i) * TBL_STRIDE, e[i]);
        }

#pragma unroll
        for (int l = 9; l < 16; l++) {
            const int slot = (l - 6) % 3;        // slot holding level l-3
            consume(g[slot], e[slot], &my[3 + 2 * (l - 3)]);
            g[slot] = make_geom(x0, x1, x2, prm.res[l]);
            load_hashed(g[slot], tbase + (size_t)l * TBL_STRIDE, e[slot]);
        }

#pragma unroll
        for (int l = 13; l < 16; l++) {
            const int slot = (l - 6) % 3;
            consume(g[slot], e[slot], &my[3 + 2 * l]);
        }
    }

    __syncwarp();

    // Coalesced writeout: each warp copies its 32 rows (32*35 floats = 4480 B,
    // 16B-aligned in smem and gmem) as float4 streaming stores.
    const int lane = threadIdx.x & 31;
    const int warp_first = (blockIdx.x * THREADS) + (threadIdx.x & ~31);
    const float4* src = (const float4*)&stage[(threadIdx.x & ~31) * OUT_COMPS];
    float4* dst = (float4*)(out + (size_t)warp_first * OUT_COMPS);
#pragma unroll
    for (int j = lane; j < (32 * OUT_COMPS) / 4; j += 32) {
        __stcs(&dst[j], src[j]);
    }
}

extern "C" void kernel_launch(void* const* d_in, const int* in_sizes, int n_in,
                              void* d_out, int out_size) {
    const float*  x      = (const float*)d_in[0];
    const float2* tables = (const float2*)d_in[1];
    float*        out    = (float*)d_out;

    // Level params via the exact same double-precision libm sequence as the
    // Python reference (same machine/libm => bit-identical results).
    Params prm;
    const double beta = exp((log(2048.0) - log(16.0)) / 15.0);
    for (int l = 0; l < N_LEVELS; l++) {
        const double r = floor(16.0 * pow(beta, (double)l));
        prm.res[l] = (float)r;
        const long long ri = (long long)r;
        long long h3 = ri * ri * ri;
        if (h3 > 524288LL) h3 = 524288LL;
        const unsigned d = (unsigned)h3;
        prm.hms[l] = d;
        prm.magic[l] = 0xFFFFFFFFFFFFFFFFull / d + 1ull;
    }

    const int npts = in_sizes[0] / 3;
    const int blocks = (npts + THREADS - 1) / THREADS;
    hashgrid_kernel<<<blocks, THREADS>>>(x, tables, out, prm);
}

// round 16
// speedup vs baseline: 1.7657x; 1.0036x over previous
#include <cuda_runtime.h>
#include <cmath>
#include <cstdint>

#define N_LEVELS 16
#define TBL_STRIDE 524288u   // 2^19 entries per level
#define OUT_COMPS 35         // 3 (x passthrough) + 16*2 feats
#define THREADS 256
#define HASH_MASK 524287u    // 2^19 - 1; levels >= 6 are always fully hashed

struct Params {
    float res[N_LEVELS];
    unsigned hms[N_LEVELS];
    unsigned long long magic[N_LEVELS];
};

// Lemire fastmod: n % d with M = 2^64/d + 1 (exact for all n < 2^32)
__device__ __forceinline__ unsigned fastmod(unsigned n, unsigned d, unsigned long long M) {
    unsigned long long low = M * (unsigned long long)n;
    return (unsigned)__umul64hi(low, (unsigned long long)d);
}

// Per-level geometry.
struct LevelGeom {
    unsigned a0, hb0, hb1, hc0, hc1;
    float fx, fy, fz;
};

__device__ __forceinline__ LevelGeom make_geom(float x0, float x1, float x2, float r) {
    const unsigned P1 = 2654435761u;
    const unsigned P2 = 805459861u;
    LevelGeom g;
    const float xs0 = x0 * r, xs1 = x1 * r, xs2 = x2 * r;
    const float fl0 = floorf(xs0), fl1 = floorf(xs1), fl2 = floorf(xs2);
    g.fx = xs0 - fl0; g.fy = xs1 - fl1; g.fz = xs2 - fl2;
    g.a0  = (unsigned)(int)fl0;
    g.hb0 = (unsigned)(int)fl1 * P1;  g.hb1 = g.hb0 + P1;
    g.hc0 = (unsigned)(int)fl2 * P2;  g.hc1 = g.hc0 + P2;
    return g;
}

// Fully-hashed level (d = 2^19, mask-mod).
__device__ __forceinline__ void load_hashed(const LevelGeom& g,
                                            const float2* __restrict__ tb,
                                            float2 e[8]) {
    const unsigned hb[2] = {g.hb0, g.hb1};
    const unsigned hc[2] = {g.hc0, g.hc1};
    if ((g.a0 & 1u) == 0u) {
#pragma unroll
        for (int pr = 0; pr < 4; pr++) {
            const int iy = pr & 1, iz = pr >> 1;
            const unsigned m0 = (g.a0 ^ hb[iy] ^ hc[iz]) & HASH_MASK;
            const float4 q = __ldcg((const float4*)tb + (m0 >> 1));
            const float2 lo = make_float2(q.x, q.y);
            const float2 hi = make_float2(q.z, q.w);
            const bool odd = (m0 & 1u) != 0u;
            const int n = (iy << 1) | (iz << 2);
            e[n]     = odd ? hi : lo;
            e[n | 1] = odd ? lo : hi;
        }
    } else {
#pragma unroll
        for (int pr = 0; pr < 4; pr++) {
            const int iy = pr & 1, iz = pr >> 1;
            const unsigned hbc = hb[iy] ^ hc[iz];
            const int n = (iy << 1) | (iz << 2);
            e[n]     = __ldcg(tb + ((g.a0 ^ hbc) & HASH_MASK));
            e[n | 1] = __ldcg(tb + (((g.a0 + 1u) ^ hbc) & HASH_MASK));
        }
    }
}

// Mod level. EVEN_D: even hms => a0-even guarantees aligned pair (parity
// preserved by even-d mod). Otherwise runtime merge check. L1: allocate in L1.
template <bool EVEN_D, bool L1>
__device__ __forceinline__ void load_mod(const LevelGeom& g,
                                         const float2* __restrict__ tb,
                                         unsigned d, unsigned long long M,
                                         float2 e[8]) {
    const unsigned hb[2] = {g.hb0, g.hb1};
    const unsigned hc[2] = {g.hc0, g.hc1};
    if (EVEN_D && (g.a0 & 1u) == 0u) {
#pragma unroll
        for (int pr = 0; pr < 4; pr++) {
            const int iy = pr & 1, iz = pr >> 1;
            const unsigned m0 = fastmod(g.a0 ^ hb[iy] ^ hc[iz], d, M);
            const float4 q = L1 ? __ldg((const float4*)tb + (m0 >> 1))
                                : __ldcg((const float4*)tb + (m0 >> 1));
            const float2 lo = make_float2(q.x, q.y);
            const float2 hi = make_float2(q.z, q.w);
            const bool odd = (m0 & 1u) != 0u;
            const int n = (iy << 1) | (iz << 2);
            e[n]     = odd ? hi : lo;
            e[n | 1] = odd ? lo : hi;
        }
    } else if (EVEN_D) {
#pragma unroll
        for (int pr = 0; pr < 4; pr++) {
            const int iy = pr & 1, iz = pr >> 1;
            const unsigned hbc = hb[iy] ^ hc[iz];
            const unsigned m0 = fastmod(g.a0 ^ hbc, d, M);
            const unsigned m1 = fastmod((g.a0 + 1u) ^ hbc, d, M);
            const int n = (iy << 1) | (iz << 2);
            e[n]     = L1 ? __ldg(tb + m0) : __ldcg(tb + m0);
            e[n | 1] = L1 ? __ldg(tb + m1) : __ldcg(tb + m1);
        }
    } else {
#pragma unroll
        for (int pr = 0; pr < 4; pr++) {
            const int iy = pr & 1, iz = pr >> 1;
            const unsigned hbc = hb[iy] ^ hc[iz];
            const unsigned m0 = fastmod(g.a0 ^ hbc, d, M);
            const unsigned m1 = fastmod((g.a0 + 1u) ^ hbc, d, M);
            const int n = (iy << 1) | (iz << 2);
            if ((m0 ^ m1) == 1u) {
                const float4 q = __ldcg((const float4*)tb + (m0 >> 1));
                const float2 lo = make_float2(q.x, q.y);
                const float2 hi = make_float2(q.z, q.w);
                const bool odd = (m0 & 1u) != 0u;
                e[n]     = odd ? hi : lo;
                e[n | 1] = odd ? lo : hi;
            } else {
                e[n]     = __ldcg(tb + m0);
                e[n | 1] = __ldcg(tb + m1);
            }
        }
    }
}

// Compile-time-folded per-level dispatch (l is constant inside #pragma unroll).
// hms: l0=4096(e) l1=10648(e) l2=27000(e) l3=68921(o) l4=185193(o) l5=512000(e)
__device__ __forceinline__ void load_any(int l, const LevelGeom& g,
                                         const float2* __restrict__ tbase,
                                         const Params& prm, float2 e[8]) {
    const float2* __restrict__ tb = tbase + (size_t)l * TBL_STRIDE;
    if (l >= 6) {
        load_hashed(g, tb, e);
    } else if (l == 3 || l == 4) {
        load_mod<false, false>(g, tb, prm.hms[l], prm.magic[l], e);
    } else if (l < 3) {
        load_mod<true, true>(g, tb, prm.hms[l], prm.magic[l], e);
    } else {  // l == 5
        load_mod<true, false>(g, tb, prm.hms[l], prm.magic[l], e);
    }
}

__device__ __forceinline__ void consume(const LevelGeom& g, const float2 e[8],
                                        float* dst) {
    const float wx[2] = {1.0f - g.fx, g.fx};
    const float wy[2] = {1.0f - g.fy, g.fy};
    const float wz[2] = {1.0f - g.fz, g.fz};
    float acc0 = 0.0f, acc1 = 0.0f;
#pragma unroll
    for (int n = 0; n < 8; n++) {
        const float w = wx[n & 1] * wy[(n >> 1) & 1] * wz[n >> 2];
        acc0 = fmaf(e[n].x, w, acc0);
        acc1 = fmaf(e[n].y, w, acc1);
    }
    dst[0] = acc0;
    dst[1] = acc1;
}

__global__ __launch_bounds__(THREADS, 3)
void hashgrid_kernel(const float* __restrict__ x,
                     const float2* __restrict__ tables,
                     float* __restrict__ out,
                     Params prm) {
    __shared__ float stage[THREADS * OUT_COMPS];

    const int pt = blockIdx.x * THREADS + threadIdx.x;

    const float x0 = x[pt * 3 + 0];
    const float x1 = x[pt * 3 + 1];
    const float x2 = x[pt * 3 + 2];

    float* my = &stage[threadIdx.x * OUT_COMPS];
    my[0] = x0; my[1] = x1; my[2] = x2;

    const float2* __restrict__ tbase = tables;

    // ── All 16 levels: depth-3 software-pipelined sliding window.
    // Prologue loads levels 0,1,2; steady state consumes level l-3 and issues
    // level l's loads into the freed slot; epilogue consumes 13,14,15.
    // 2-3 levels' gathers stay in flight at all times — no drain bubbles at
    // level boundaries, including the mod->hashed transition.
    {
        LevelGeom g[3];
        float2 e[3][8];

#pragma unroll
        for (int i = 0; i < 3; i++) {
            g[i] = make_geom(x0, x1, x2, prm.res[i]);
            load_any(i, g[i], tbase, prm, e[i]);
        }

#pragma unroll
        for (int l = 3; l < 16; l++) {
            const int slot = l % 3;              // slot holding level l-3
            consume(g[slot], e[slot], &my[3 + 2 * (l - 3)]);
            g[slot] = make_geom(x0, x1, x2, prm.res[l]);
            load_any(l, g[slot], tbase, prm, e[slot]);
        }

#pragma unroll
        for (int l = 13; l < 16; l++) {
            const int slot = l % 3;
            consume(g[slot], e[slot], &my[3 + 2 * l]);
        }
    }

    __syncwarp();

    // Coalesced writeout: each warp copies its 32 rows (32*35 floats = 4480 B,
    // 16B-aligned in smem and gmem) as float4 streaming stores.
    const int lane = threadIdx.x & 31;
    const int warp_first = (blockIdx.x * THREADS) + (threadIdx.x & ~31);
    const float4* src = (const float4*)&stage[(threadIdx.x & ~31) * OUT_COMPS];
    float4* dst = (float4*)(out + (size_t)warp_first * OUT_COMPS);
#pragma unroll
    for (int j = lane; j < (32 * OUT_COMPS) / 4; j += 32) {
        __stcs(&dst[j], src[j]);
    }
}

extern "C" void kernel_launch(void* const* d_in, const int* in_sizes, int n_in,
                              void* d_out, int out_size) {
    const float*  x      = (const float*)d_in[0];
    const float2* tables = (const float2*)d_in[1];
    float*        out    = (float*)d_out;

    // Level params via the exact same double-precision libm sequence as the
    // Python reference (same machine/libm => bit-identical results).
    Params prm;
    const double beta = exp((log(2048.0) - log(16.0)) / 15.0);
    for (int l = 0; l < N_LEVELS; l++) {
        const double r = floor(16.0 * pow(beta, (double)l));
        prm.res[l] = (float)r;
        const long long ri = (long long)r;
        long long h3 = ri * ri * ri;
        if (h3 > 524288LL) h3 = 524288LL;
        const unsigned d = (unsigned)h3;
        prm.hms[l] = d;
        prm.magic[l] = 0xFFFFFFFFFFFFFFFFull / d + 1ull;
    }

    const int npts = in_sizes[0] / 3;
    const int blocks = (npts + THREADS - 1) / THREADS;
    hashgrid_kernel<<<blocks, THREADS>>>(x, tables, out, prm);
}